// round 16
// baseline (speedup 1.0000x reference)
#include <cuda_runtime.h>
#include <cuda_fp16.h>
#include <cstdint>

#define NFEAT 256
#define NHID  128
#define MAXN  100000
#define MAXE  1600000

// ---------------- scratch (no cudaMalloc allowed) ----------------
__device__ __half g_zh [MAXN * NHID];        // residual, fp16
__device__ __half g_y1h[MAXN * NHID];        // x@W1, fp16
__device__ __half g_x1h[MAXN * NHID];        // relu(spmm+b1)+z, fp16
__device__ __half g_y2h[MAXN * NHID];        // x1@W2, fp16
__device__ int    g_rowptr[MAXN + 1];
__device__ uint2  g_ep[MAXE];                // packed {col, val bits}
__device__ __half g_Bc[2 * NHID * NFEAT];    // (W_res|W1)^T fp16 [256 n][256 k]
__device__ __half g_B2[NHID * NHID];         // W2^T fp16 [128 n][128 k]

__device__ __forceinline__ uint32_t pack_h2(__half a, __half b) {
    return (uint32_t)__half_as_ushort(a) | ((uint32_t)__half_as_ushort(b) << 16);
}
__device__ __forceinline__ uint32_t smem_u32(const void* p) {
    uint32_t a;
    asm("{ .reg .u64 t; cvta.to.shared.u64 t, %1; cvt.u32.u64 %0, t; }" : "=r"(a) : "l"(p));
    return a;
}
__device__ __forceinline__ void ldsm_x4(uint32_t r[4], uint32_t saddr) {
    asm volatile("ldmatrix.sync.aligned.m8n8.x4.shared.b16 {%0,%1,%2,%3}, [%4];"
                 : "=r"(r[0]), "=r"(r[1]), "=r"(r[2]), "=r"(r[3]) : "r"(saddr));
}
__device__ __forceinline__ void cpa16(uint32_t dst, const void* src) {
    asm volatile("cp.async.cg.shared.global [%0], [%1], 16;" :: "r"(dst), "l"(src));
}
#define CP_COMMIT() asm volatile("cp.async.commit_group;" ::: "memory")
#define CP_WAIT0()  asm volatile("cp.async.wait_group 0;"  ::: "memory")
#define CP_WAIT1()  asm volatile("cp.async.wait_group 1;"  ::: "memory")

__device__ __forceinline__ void mma16816(float c[4], const uint32_t a[4], const uint32_t b[2]) {
    asm volatile(
        "mma.sync.aligned.m16n8k16.row.col.f32.f16.f16.f32 "
        "{%0,%1,%2,%3}, {%4,%5,%6,%7}, {%8,%9}, {%0,%1,%2,%3};"
        : "+f"(c[0]), "+f"(c[1]), "+f"(c[2]), "+f"(c[3])
        : "r"(a[0]), "r"(a[1]), "r"(a[2]), "r"(a[3]), "r"(b[0]), "r"(b[1]));
}

// accumulate one fp16 gather (uint2 = 4 halves) scaled by v into fp32 acc[4]
__device__ __forceinline__ void acc_gather(float* a, uint2 m, float v) {
    float2 f0 = __half22float2(*reinterpret_cast<__half2*>(&m.x));
    float2 f1 = __half22float2(*reinterpret_cast<__half2*>(&m.y));
    a[0] += v * f0.x; a[1] += v * f0.y; a[2] += v * f1.x; a[3] += v * f1.y;
}

// ---------------- prep: weights fp16 + rowptr + packed edge stream ----------------
__global__ void prep_all(const float* __restrict__ W_res, const float* __restrict__ W1,
                         const float* __restrict__ W2, const int* __restrict__ edge_row,
                         const int* __restrict__ edge_col, const float* __restrict__ edge_val,
                         int n_edges, int n_nodes) {
    const int NW  = 2 * NHID * NFEAT;
    const int NW2 = NHID * NHID;
    int idx = blockIdx.x * blockDim.x + threadIdx.x;
    if (idx < NW) {
        int n = idx >> 8, k = idx & 255;
        float w = (n < NHID) ? W_res[k * NHID + n] : W1[k * NHID + (n - NHID)];
        g_Bc[n * NFEAT + k] = __float2half_rn(w);
    } else if (idx < NW + NW2) {
        int j = idx - NW;
        int n = j >> 7, k = j & 127;
        g_B2[n * NHID + k] = __float2half_rn(W2[k * NHID + n]);
    } else {
        int e = idx - NW - NW2;
        if (e < n_edges) {
            g_ep[e] = make_uint2((uint32_t)__ldg(edge_col + e),
                                 __float_as_uint(__ldg(edge_val + e)));
            int cur  = __ldg(edge_row + e);
            int prev = (e == 0) ? -1 : __ldg(edge_row + e - 1);
            for (int r = prev + 1; r <= cur; r++) g_rowptr[r] = e;
            if (e == n_edges - 1)
                for (int r = cur + 1; r <= n_nodes; r++) g_rowptr[r] = n_edges;
        }
    }
}

#define AS 40    // gemm1 smem stride (fp16 elems; 80B, ldmatrix conflict-free)
#define AS2 136  // gemm2 smem stride for K=128 rows (272B)

// ---------------- GEMM1: A fp32, K=256 -> z fp16 (+bias) and y1 fp16 ----------------
__global__ void __launch_bounds__(256, 2) gemm_a32(
    const float* __restrict__ A, int lda, int Kfull, int n_rows,
    const __half* __restrict__ B,
    __half* __restrict__ Cz, __half* __restrict__ Ch, const float* __restrict__ bias0)
{
    constexpr uint32_t aBytes = 128 * AS * 2;
    constexpr uint32_t offB   = 2 * aBytes;
    constexpr uint32_t bBytes = 128 * AS * 2;
    extern __shared__ __half sm[];
    const uint32_t sbase = smem_u32(sm);

    const int tid = threadIdx.x, wid = tid >> 5, lane = tid & 31;
    const int g = lane >> 2, tig = lane & 3;
    const int warp_m = wid & 3, warp_n = wid >> 2;
    const int row0 = blockIdx.y * 128;
    const int half = blockIdx.x;
    const __half* BT = B + (size_t)half * 128 * Kfull;

    float acc[2][8][4];
    #pragma unroll
    for (int i = 0; i < 2; i++)
        #pragma unroll
        for (int j = 0; j < 8; j++)
            #pragma unroll
            for (int q = 0; q < 4; q++) acc[i][j][q] = 0.f;

    const int a_row = (lane & 7) + ((lane >> 3) & 1) * 8;
    const int a_col = ((lane >> 4) & 1) * 8;
    const int b_row = (lane & 7) + ((lane >> 4) & 1) * 8;
    const int b_col = ((lane >> 3) & 1) * 8;

    const int nchunks = Kfull >> 5;
    float4 va[4];

    auto loadA = [&](int kc) {
        #pragma unroll
        for (int it = 0; it < 4; it++) {
            int idx = it * 256 + tid;
            int r = idx >> 3, q = idx & 7;
            int grow = row0 + r;
            va[it] = make_float4(0.f, 0.f, 0.f, 0.f);
            if (grow < n_rows)
                va[it] = *reinterpret_cast<const float4*>(A + (size_t)grow * lda + kc * 32 + q * 4);
        }
    };
    auto storeA = [&](int buf) {
        __half* Ap = sm + (size_t)buf * (aBytes / 2);
        #pragma unroll
        for (int it = 0; it < 4; it++) {
            int idx = it * 256 + tid;
            int r = idx >> 3, q = idx & 7;
            float4 v = va[it];
            *reinterpret_cast<uint2*>(&Ap[r * AS + q * 4]) =
                make_uint2(pack_h2(__float2half_rn(v.x), __float2half_rn(v.y)),
                           pack_h2(__float2half_rn(v.z), __float2half_rn(v.w)));
        }
    };
    auto cpB = [&](int kc, int buf) {
        uint32_t bp = sbase + offB + buf * bBytes;
        #pragma unroll
        for (int it = 0; it < 2; it++) {
            int idx = it * 256 + tid;
            int r = idx >> 2, q = idx & 3;
            size_t src = (size_t)r * Kfull + kc * 32 + q * 8;
            cpa16(bp + (uint32_t)(r * AS + q * 8) * 2, BT + src);
        }
    };

    loadA(0);
    cpB(0, 0); CP_COMMIT();
    storeA(0);
    CP_WAIT0();
    __syncthreads();

    for (int kc = 0; kc < nchunks; kc++) {
        const int buf = kc & 1;
        const bool nb = (kc + 1 < nchunks);
        if (nb) { loadA(kc + 1); cpB(kc + 1, buf ^ 1); CP_COMMIT(); }

        const uint32_t aP = sbase + buf * aBytes;
        const uint32_t bP = sbase + offB + buf * bBytes;

        #pragma unroll
        for (int ks = 0; ks < 32; ks += 16) {
            uint32_t ah[2][4];
            #pragma unroll
            for (int mf = 0; mf < 2; mf++) {
                int rb = warp_m * 32 + mf * 16;
                ldsm_x4(ah[mf], aP + (uint32_t)((rb + a_row) * AS + ks + a_col) * 2);
            }
            #pragma unroll
            for (int p = 0; p < 4; p++) {
                int n0 = warp_n * 64 + p * 16;
                uint32_t b4[4];
                ldsm_x4(b4, bP + (uint32_t)((n0 + b_row) * AS + ks + b_col) * 2);
                #pragma unroll
                for (int mf = 0; mf < 2; mf++) {
                    mma16816(acc[mf][2 * p],     ah[mf], &b4[0]);
                    mma16816(acc[mf][2 * p + 1], ah[mf], &b4[2]);
                }
            }
        }

        if (nb) { storeA(buf ^ 1); CP_WAIT0(); }
        __syncthreads();
    }

    __half* dest = (half == 0) ? Cz : Ch;
    #pragma unroll
    for (int mf = 0; mf < 2; mf++) {
        int r_lo = row0 + warp_m * 32 + mf * 16 + g;
        int r_hi = r_lo + 8;
        #pragma unroll
        for (int nf = 0; nf < 8; nf++) {
            int col = warp_n * 64 + nf * 8 + tig * 2;
            float bx = 0.f, by = 0.f;
            if (half == 0) { bx = bias0[col]; by = bias0[col + 1]; }
            if (r_lo < n_rows)
                *reinterpret_cast<uint32_t*>(dest + (size_t)r_lo * NHID + col) =
                    pack_h2(__float2half_rn(acc[mf][nf][0] + bx), __float2half_rn(acc[mf][nf][1] + by));
            if (r_hi < n_rows)
                *reinterpret_cast<uint32_t*>(dest + (size_t)r_hi * NHID + col) =
                    pack_h2(__float2half_rn(acc[mf][nf][2] + bx), __float2half_rn(acc[mf][nf][3] + by));
        }
    }
}

// ---------------- GEMM2: split-K pipelined K=128, A fp16, B fp16 -> y2 fp16 ----------------
__global__ void __launch_bounds__(256, 2) gemm2_k128(
    const __half* __restrict__ A, int n_rows,
    const __half* __restrict__ B, __half* __restrict__ C)
{
    constexpr uint32_t matBytes = 128 * AS2 * 2;   // 34816
    extern __shared__ __half sm[];
    const uint32_t sbase = smem_u32(sm);
    const uint32_t aP = sbase;
    const uint32_t bP = sbase + matBytes;

    const int tid = threadIdx.x, wid = tid >> 5, lane = tid & 31;
    const int g = lane >> 2, tig = lane & 3;
    const int warp_m = wid & 3, warp_n = wid >> 2;
    const int row0 = blockIdx.x * 128;

    float acc[2][8][4];
    #pragma unroll
    for (int i = 0; i < 2; i++)
        #pragma unroll
        for (int j = 0; j < 8; j++)
            #pragma unroll
            for (int q = 0; q < 4; q++) acc[i][j][q] = 0.f;

    const int a_row = (lane & 7) + ((lane >> 3) & 1) * 8;
    const int a_col = ((lane >> 4) & 1) * 8;
    const int b_row = (lane & 7) + ((lane >> 4) & 1) * 8;
    const int b_col = ((lane >> 3) & 1) * 8;

    auto fillHalf = [&](int colbase) {
        #pragma unroll
        for (int it = 0; it < 4; it++) {
            int idx = it * 256 + tid;
            int r = idx >> 3, q = idx & 7;
            int c = colbase + q * 8;
            cpa16(aP + (uint32_t)(r * AS2 + c) * 2, A + (size_t)(row0 + r) * NHID + c);
        }
        #pragma unroll
        for (int it = 0; it < 4; it++) {
            int idx = it * 256 + tid;
            int r = idx >> 3, q = idx & 7;
            int c = colbase + q * 8;
            cpa16(bP + (uint32_t)(r * AS2 + c) * 2, B + (size_t)r * NHID + c);
        }
    };

    fillHalf(0);  CP_COMMIT();
    fillHalf(64); CP_COMMIT();

    CP_WAIT1();
    __syncthreads();

    auto computeHalf = [&](int ksbase) {
        #pragma unroll
        for (int ks0 = 0; ks0 < 64; ks0 += 16) {
            int ks = ksbase + ks0;
            uint32_t ah[2][4];
            #pragma unroll
            for (int mf = 0; mf < 2; mf++) {
                int rb = warp_m * 32 + mf * 16;
                ldsm_x4(ah[mf], aP + (uint32_t)((rb + a_row) * AS2 + ks + a_col) * 2);
            }
            #pragma unroll
            for (int p = 0; p < 4; p++) {
                int n0 = warp_n * 64 + p * 16;
                uint32_t b4[4];
                ldsm_x4(b4, bP + (uint32_t)((n0 + b_row) * AS2 + ks + b_col) * 2);
                #pragma unroll
                for (int mf = 0; mf < 2; mf++) {
                    mma16816(acc[mf][2 * p],     ah[mf], &b4[0]);
                    mma16816(acc[mf][2 * p + 1], ah[mf], &b4[2]);
                }
            }
        }
    };

    computeHalf(0);
    CP_WAIT0();
    __syncthreads();
    computeHalf(64);

    #pragma unroll
    for (int mf = 0; mf < 2; mf++) {
        int r_lo = row0 + warp_m * 32 + mf * 16 + g;
        int r_hi = r_lo + 8;
        #pragma unroll
        for (int nf = 0; nf < 8; nf++) {
            int col = warp_n * 64 + nf * 8 + tig * 2;
            if (r_lo < n_rows)
                *reinterpret_cast<uint32_t*>(C + (size_t)r_lo * NHID + col) =
                    pack_h2(__float2half_rn(acc[mf][nf][0]), __float2half_rn(acc[mf][nf][1]));
            if (r_hi < n_rows)
                *reinterpret_cast<uint32_t*>(C + (size_t)r_hi * NHID + col) =
                    pack_h2(__float2half_rn(acc[mf][nf][2]), __float2half_rn(acc[mf][nf][3]));
        }
    }
}

// ---------------- SpMM #1 (packed edges, unroll-8) + relu + residual(fp16) ----------------
__global__ void spmm_relu_res(const float* __restrict__ b1, int n) {
    int w = (blockIdx.x * blockDim.x + threadIdx.x) >> 5;
    int lane = threadIdx.x & 31;
    if (w >= n) return;
    int s = g_rowptr[w], e = g_rowptr[w + 1];
    const uint2* src = reinterpret_cast<const uint2*>(g_y1h);
    float a0[4] = {0.f, 0.f, 0.f, 0.f}, a1[4] = {0.f, 0.f, 0.f, 0.f};
    int i = s;
    for (; i + 7 < e; i += 8) {
        uint2 p0 = __ldg(g_ep + i),     p1 = __ldg(g_ep + i + 1);
        uint2 p2 = __ldg(g_ep + i + 2), p3 = __ldg(g_ep + i + 3);
        uint2 p4 = __ldg(g_ep + i + 4), p5 = __ldg(g_ep + i + 5);
        uint2 p6 = __ldg(g_ep + i + 6), p7 = __ldg(g_ep + i + 7);
        uint2 m0 = __ldg(src + (size_t)p0.x * 32 + lane);
        uint2 m1 = __ldg(src + (size_t)p1.x * 32 + lane);
        uint2 m2 = __ldg(src + (size_t)p2.x * 32 + lane);
        uint2 m3 = __ldg(src + (size_t)p3.x * 32 + lane);
        uint2 m4 = __ldg(src + (size_t)p4.x * 32 + lane);
        uint2 m5 = __ldg(src + (size_t)p5.x * 32 + lane);
        uint2 m6 = __ldg(src + (size_t)p6.x * 32 + lane);
        uint2 m7 = __ldg(src + (size_t)p7.x * 32 + lane);
        acc_gather(a0, m0, __uint_as_float(p0.y));
        acc_gather(a1, m1, __uint_as_float(p1.y));
        acc_gather(a0, m2, __uint_as_float(p2.y));
        acc_gather(a1, m3, __uint_as_float(p3.y));
        acc_gather(a0, m4, __uint_as_float(p4.y));
        acc_gather(a1, m5, __uint_as_float(p5.y));
        acc_gather(a0, m6, __uint_as_float(p6.y));
        acc_gather(a1, m7, __uint_as_float(p7.y));
    }
    if (i + 3 < e) {
        uint2 p0 = __ldg(g_ep + i),     p1 = __ldg(g_ep + i + 1);
        uint2 p2 = __ldg(g_ep + i + 2), p3 = __ldg(g_ep + i + 3);
        uint2 m0 = __ldg(src + (size_t)p0.x * 32 + lane);
        uint2 m1 = __ldg(src + (size_t)p1.x * 32 + lane);
        uint2 m2 = __ldg(src + (size_t)p2.x * 32 + lane);
        uint2 m3 = __ldg(src + (size_t)p3.x * 32 + lane);
        acc_gather(a0, m0, __uint_as_float(p0.y));
        acc_gather(a1, m1, __uint_as_float(p1.y));
        acc_gather(a0, m2, __uint_as_float(p2.y));
        acc_gather(a1, m3, __uint_as_float(p3.y));
        i += 4;
    }
    if (i + 1 < e) {
        uint2 p0 = __ldg(g_ep + i), p1 = __ldg(g_ep + i + 1);
        uint2 m0 = __ldg(src + (size_t)p0.x * 32 + lane);
        uint2 m1 = __ldg(src + (size_t)p1.x * 32 + lane);
        acc_gather(a0, m0, __uint_as_float(p0.y));
        acc_gather(a1, m1, __uint_as_float(p1.y));
        i += 2;
    }
    if (i < e) {
        uint2 p = __ldg(g_ep + i);
        uint2 m = __ldg(src + (size_t)p.x * 32 + lane);
        acc_gather(a0, m, __uint_as_float(p.y));
    }
    #pragma unroll
    for (int q = 0; q < 4; q++) a0[q] += a1[q];
    float4 bb = reinterpret_cast<const float4*>(b1)[lane];
    uint2 zz = reinterpret_cast<const uint2*>(g_zh)[(size_t)w * 32 + lane];
    float2 z0 = __half22float2(*reinterpret_cast<__half2*>(&zz.x));
    float2 z1 = __half22float2(*reinterpret_cast<__half2*>(&zz.y));
    float rx = fmaxf(a0[0] + bb.x, 0.f) + z0.x;
    float ry = fmaxf(a0[1] + bb.y, 0.f) + z0.y;
    float rz = fmaxf(a0[2] + bb.z, 0.f) + z1.x;
    float rw = fmaxf(a0[3] + bb.w, 0.f) + z1.y;
    uint2 o = make_uint2(pack_h2(__float2half_rn(rx), __float2half_rn(ry)),
                         pack_h2(__float2half_rn(rz), __float2half_rn(rw)));
    reinterpret_cast<uint2*>(g_x1h)[(size_t)w * 32 + lane] = o;
}

// ---------------- SpMM #2 (packed edges, unroll-8) + bias + log_softmax ----------------
__global__ void spmm_logsoftmax(const float* __restrict__ b2, float* __restrict__ out, int n) {
    int w = (blockIdx.x * blockDim.x + threadIdx.x) >> 5;
    int lane = threadIdx.x & 31;
    if (w >= n) return;
    int s = g_rowptr[w], e = g_rowptr[w + 1];
    const uint2* src = reinterpret_cast<const uint2*>(g_y2h);
    float a0[4] = {0.f, 0.f, 0.f, 0.f}, a1[4] = {0.f, 0.f, 0.f, 0.f};
    int i = s;
    for (; i + 7 < e; i += 8) {
        uint2 p0 = __ldg(g_ep + i),     p1 = __ldg(g_ep + i + 1);
        uint2 p2 = __ldg(g_ep + i + 2), p3 = __ldg(g_ep + i + 3);
        uint2 p4 = __ldg(g_ep + i + 4), p5 = __ldg(g_ep + i + 5);
        uint2 p6 = __ldg(g_ep + i + 6), p7 = __ldg(g_ep + i + 7);
        uint2 m0 = __ldg(src + (size_t)p0.x * 32 + lane);
        uint2 m1 = __ldg(src + (size_t)p1.x * 32 + lane);
        uint2 m2 = __ldg(src + (size_t)p2.x * 32 + lane);
        uint2 m3 = __ldg(src + (size_t)p3.x * 32 + lane);
        uint2 m4 = __ldg(src + (size_t)p4.x * 32 + lane);
        uint2 m5 = __ldg(src + (size_t)p5.x * 32 + lane);
        uint2 m6 = __ldg(src + (size_t)p6.x * 32 + lane);
        uint2 m7 = __ldg(src + (size_t)p7.x * 32 + lane);
        acc_gather(a0, m0, __uint_as_float(p0.y));
        acc_gather(a1, m1, __uint_as_float(p1.y));
        acc_gather(a0, m2, __uint_as_float(p2.y));
        acc_gather(a1, m3, __uint_as_float(p3.y));
        acc_gather(a0, m4, __uint_as_float(p4.y));
        acc_gather(a1, m5, __uint_as_float(p5.y));
        acc_gather(a0, m6, __uint_as_float(p6.y));
        acc_gather(a1, m7, __uint_as_float(p7.y));
    }
    if (i + 3 < e) {
        uint2 p0 = __ldg(g_ep + i),     p1 = __ldg(g_ep + i + 1);
        uint2 p2 = __ldg(g_ep + i + 2), p3 = __ldg(g_ep + i + 3);
        uint2 m0 = __ldg(src + (size_t)p0.x * 32 + lane);
        uint2 m1 = __ldg(src + (size_t)p1.x * 32 + lane);
        uint2 m2 = __ldg(src + (size_t)p2.x * 32 + lane);
        uint2 m3 = __ldg(src + (size_t)p3.x * 32 + lane);
        acc_gather(a0, m0, __uint_as_float(p0.y));
        acc_gather(a1, m1, __uint_as_float(p1.y));
        acc_gather(a0, m2, __uint_as_float(p2.y));
        acc_gather(a1, m3, __uint_as_float(p3.y));
        i += 4;
    }
    if (i + 1 < e) {
        uint2 p0 = __ldg(g_ep + i), p1 = __ldg(g_ep + i + 1);
        uint2 m0 = __ldg(src + (size_t)p0.x * 32 + lane);
        uint2 m1 = __ldg(src + (size_t)p1.x * 32 + lane);
        acc_gather(a0, m0, __uint_as_float(p0.y));
        acc_gather(a1, m1, __uint_as_float(p1.y));
        i += 2;
    }
    if (i < e) {
        uint2 p = __ldg(g_ep + i);
        uint2 m = __ldg(src + (size_t)p.x * 32 + lane);
        acc_gather(a0, m, __uint_as_float(p.y));
    }
    float4 bb = reinterpret_cast<const float4*>(b2)[lane];
    float hx = a0[0] + a1[0] + bb.x;
    float hy = a0[1] + a1[1] + bb.y;
    float hz = a0[2] + a1[2] + bb.z;
    float hw = a0[3] + a1[3] + bb.w;
    float mx = fmaxf(fmaxf(hx, hy), fmaxf(hz, hw));
    #pragma unroll
    for (int o = 16; o > 0; o >>= 1) mx = fmaxf(mx, __shfl_xor_sync(0xffffffffu, mx, o));
    float sum = expf(hx - mx) + expf(hy - mx) + expf(hz - mx) + expf(hw - mx);
    #pragma unroll
    for (int o = 16; o > 0; o >>= 1) sum += __shfl_xor_sync(0xffffffffu, sum, o);
    float lse = mx + logf(sum);
    float4 r = make_float4(hx - lse, hy - lse, hz - lse, hw - lse);
    reinterpret_cast<float4*>(out)[(size_t)w * 32 + lane] = r;
}

// ---------------- launch ----------------
extern "C" void kernel_launch(void* const* d_in, const int* in_sizes, int n_in,
                              void* d_out, int out_size) {
    const float* x        = (const float*)d_in[0];
    const int*   edge_row = (const int*)  d_in[1];
    const int*   edge_col = (const int*)  d_in[2];
    const float* edge_val = (const float*)d_in[3];
    const float* W_res    = (const float*)d_in[4];
    const float* b_res    = (const float*)d_in[5];
    const float* W1       = (const float*)d_in[6];
    const float* b1       = (const float*)d_in[7];
    const float* W2       = (const float*)d_in[8];
    const float* b2       = (const float*)d_in[9];
    float* out = (float*)d_out;
    const int n_nodes = in_sizes[0] / NFEAT;
    const int n_edges = in_sizes[1];

    __half *zp, *y1p, *x1p, *y2p, *bcp, *b2p;
    cudaGetSymbolAddress((void**)&zp,  g_zh);
    cudaGetSymbolAddress((void**)&y1p, g_y1h);
    cudaGetSymbolAddress((void**)&x1p, g_x1h);
    cudaGetSymbolAddress((void**)&y2p, g_y2h);
    cudaGetSymbolAddress((void**)&bcp, g_Bc);
    cudaGetSymbolAddress((void**)&b2p, g_B2);

    const int gemm1_smem = 4 * 128 * AS * 2;      // 40960
    const int gemm2_smem = 2 * 128 * AS2 * 2;     // 69632
    cudaFuncSetAttribute(gemm_a32,   cudaFuncAttributeMaxDynamicSharedMemorySize, gemm1_smem);
    cudaFuncSetAttribute(gemm2_k128, cudaFuncAttributeMaxDynamicSharedMemorySize, gemm2_smem);

    const int prep_threads = 2 * NHID * NFEAT + NHID * NHID + n_edges;
    prep_all<<<(prep_threads + 255) / 256, 256>>>(W_res, W1, W2, edge_row, edge_col, edge_val,
                                                  n_edges, n_nodes);

    const int gx = (n_nodes + 127) / 128;
    dim3 g1(2, gx);
    gemm_a32<<<g1, 256, gemm1_smem>>>(x, NFEAT, NFEAT, n_nodes, bcp, zp, y1p, b_res);

    spmm_relu_res<<<(n_nodes * 32 + 255) / 256, 256>>>(b1, n_nodes);

    gemm2_k128<<<gx, 256, gemm2_smem>>>(x1p, n_nodes, b2p, y2p);

    spmm_logsoftmax<<<(n_nodes * 32 + 255) / 256, 256>>>(b2, out, n_nodes);
}

// round 17
// speedup vs baseline: 1.1145x; 1.1145x over previous
#include <cuda_runtime.h>
#include <cuda_fp16.h>
#include <cstdint>

#define NFEAT 256
#define NHID  128
#define MAXN  100000

// ---------------- scratch (no cudaMalloc allowed) ----------------
__device__ __half g_zh [MAXN * NHID];        // residual, fp16
__device__ __half g_y1h[MAXN * NHID];        // x@W1, fp16
__device__ __half g_x1h[MAXN * NHID];        // relu(spmm+b1)+z, fp16
__device__ __half g_y2h[MAXN * NHID];        // x1@W2, fp16
__device__ int    g_rowptr[MAXN + 1];
__device__ __half g_Bc[2 * NHID * NFEAT];    // (W_res|W1)^T fp16 [256 n][256 k]
__device__ __half g_B2[NHID * NHID];         // W2^T fp16 [128 n][128 k]

__device__ __forceinline__ uint32_t pack_h2(__half a, __half b) {
    return (uint32_t)__half_as_ushort(a) | ((uint32_t)__half_as_ushort(b) << 16);
}
__device__ __forceinline__ uint32_t smem_u32(const void* p) {
    uint32_t a;
    asm("{ .reg .u64 t; cvta.to.shared.u64 t, %1; cvt.u32.u64 %0, t; }" : "=r"(a) : "l"(p));
    return a;
}
__device__ __forceinline__ void ldsm_x4(uint32_t r[4], uint32_t saddr) {
    asm volatile("ldmatrix.sync.aligned.m8n8.x4.shared.b16 {%0,%1,%2,%3}, [%4];"
                 : "=r"(r[0]), "=r"(r[1]), "=r"(r[2]), "=r"(r[3]) : "r"(saddr));
}
__device__ __forceinline__ void cpa16(uint32_t dst, const void* src) {
    asm volatile("cp.async.cg.shared.global [%0], [%1], 16;" :: "r"(dst), "l"(src));
}
#define CP_COMMIT() asm volatile("cp.async.commit_group;" ::: "memory")
#define CP_WAIT0()  asm volatile("cp.async.wait_group 0;"  ::: "memory")
#define CP_WAIT1()  asm volatile("cp.async.wait_group 1;"  ::: "memory")

__device__ __forceinline__ void mma16816(float c[4], const uint32_t a[4], const uint32_t b[2]) {
    asm volatile(
        "mma.sync.aligned.m16n8k16.row.col.f32.f16.f16.f32 "
        "{%0,%1,%2,%3}, {%4,%5,%6,%7}, {%8,%9}, {%0,%1,%2,%3};"
        : "+f"(c[0]), "+f"(c[1]), "+f"(c[2]), "+f"(c[3])
        : "r"(a[0]), "r"(a[1]), "r"(a[2]), "r"(a[3]), "r"(b[0]), "r"(b[1]));
}

// accumulate one fp16 gather (uint2 = 4 halves) scaled by v into fp32 acc[4]
__device__ __forceinline__ void acc_gather(float* a, uint2 m, float v) {
    float2 f0 = __half22float2(*reinterpret_cast<__half2*>(&m.x));
    float2 f1 = __half22float2(*reinterpret_cast<__half2*>(&m.y));
    a[0] += v * f0.x; a[1] += v * f0.y; a[2] += v * f1.x; a[3] += v * f1.y;
}

// ---------------- prep: weight fp16 transpose + rowptr (boundary scatter) ----------------
__global__ void prep_all(const float* __restrict__ W_res, const float* __restrict__ W1,
                         const float* __restrict__ W2, const int* __restrict__ edge_row,
                         int n_edges, int n_nodes) {
    const int NW  = 2 * NHID * NFEAT;
    const int NW2 = NHID * NHID;
    int idx = blockIdx.x * blockDim.x + threadIdx.x;
    if (idx < NW) {
        int n = idx >> 8, k = idx & 255;
        float w = (n < NHID) ? W_res[k * NHID + n] : W1[k * NHID + (n - NHID)];
        g_Bc[n * NFEAT + k] = __float2half_rn(w);
    } else if (idx < NW + NW2) {
        int j = idx - NW;
        int n = j >> 7, k = j & 127;
        g_B2[n * NHID + k] = __float2half_rn(W2[k * NHID + n]);
    } else {
        int e = idx - NW - NW2;
        if (e < n_edges) {
            int cur  = __ldg(edge_row + e);
            int prev = (e == 0) ? -1 : __ldg(edge_row + e - 1);
            for (int r = prev + 1; r <= cur; r++) g_rowptr[r] = e;
            if (e == n_edges - 1)
                for (int r = cur + 1; r <= n_nodes; r++) g_rowptr[r] = n_edges;
        }
    }
}

#define AS 40    // gemm1 smem stride (fp16 elems; 80B, ldmatrix conflict-free)
#define AS2 136  // gemm2 smem stride for K=128 rows (272B)

// ---------------- GEMM1: A fp32, K=256 -> z fp16 (+bias) and y1 fp16 ----------------
__global__ void __launch_bounds__(256, 2) gemm_a32(
    const float* __restrict__ A, int lda, int Kfull, int n_rows,
    const __half* __restrict__ B,
    __half* __restrict__ Cz, __half* __restrict__ Ch, const float* __restrict__ bias0)
{
    constexpr uint32_t aBytes = 128 * AS * 2;
    constexpr uint32_t offB   = 2 * aBytes;
    constexpr uint32_t bBytes = 128 * AS * 2;
    extern __shared__ __half sm[];
    const uint32_t sbase = smem_u32(sm);

    const int tid = threadIdx.x, wid = tid >> 5, lane = tid & 31;
    const int g = lane >> 2, tig = lane & 3;
    const int warp_m = wid & 3, warp_n = wid >> 2;
    const int row0 = blockIdx.y * 128;
    const int half = blockIdx.x;
    const __half* BT = B + (size_t)half * 128 * Kfull;

    float acc[2][8][4];
    #pragma unroll
    for (int i = 0; i < 2; i++)
        #pragma unroll
        for (int j = 0; j < 8; j++)
            #pragma unroll
            for (int q = 0; q < 4; q++) acc[i][j][q] = 0.f;

    const int a_row = (lane & 7) + ((lane >> 3) & 1) * 8;
    const int a_col = ((lane >> 4) & 1) * 8;
    const int b_row = (lane & 7) + ((lane >> 4) & 1) * 8;
    const int b_col = ((lane >> 3) & 1) * 8;

    const int nchunks = Kfull >> 5;
    float4 va[4];

    auto loadA = [&](int kc) {
        #pragma unroll
        for (int it = 0; it < 4; it++) {
            int idx = it * 256 + tid;
            int r = idx >> 3, q = idx & 7;
            int grow = row0 + r;
            va[it] = make_float4(0.f, 0.f, 0.f, 0.f);
            if (grow < n_rows)
                va[it] = *reinterpret_cast<const float4*>(A + (size_t)grow * lda + kc * 32 + q * 4);
        }
    };
    auto storeA = [&](int buf) {
        __half* Ap = sm + (size_t)buf * (aBytes / 2);
        #pragma unroll
        for (int it = 0; it < 4; it++) {
            int idx = it * 256 + tid;
            int r = idx >> 3, q = idx & 7;
            float4 v = va[it];
            *reinterpret_cast<uint2*>(&Ap[r * AS + q * 4]) =
                make_uint2(pack_h2(__float2half_rn(v.x), __float2half_rn(v.y)),
                           pack_h2(__float2half_rn(v.z), __float2half_rn(v.w)));
        }
    };
    auto cpB = [&](int kc, int buf) {
        uint32_t bp = sbase + offB + buf * bBytes;
        #pragma unroll
        for (int it = 0; it < 2; it++) {
            int idx = it * 256 + tid;
            int r = idx >> 2, q = idx & 3;
            size_t src = (size_t)r * Kfull + kc * 32 + q * 8;
            cpa16(bp + (uint32_t)(r * AS + q * 8) * 2, BT + src);
        }
    };

    loadA(0);
    cpB(0, 0); CP_COMMIT();
    storeA(0);
    CP_WAIT0();
    __syncthreads();

    for (int kc = 0; kc < nchunks; kc++) {
        const int buf = kc & 1;
        const bool nb = (kc + 1 < nchunks);
        if (nb) { loadA(kc + 1); cpB(kc + 1, buf ^ 1); CP_COMMIT(); }

        const uint32_t aP = sbase + buf * aBytes;
        const uint32_t bP = sbase + offB + buf * bBytes;

        #pragma unroll
        for (int ks = 0; ks < 32; ks += 16) {
            uint32_t ah[2][4];
            #pragma unroll
            for (int mf = 0; mf < 2; mf++) {
                int rb = warp_m * 32 + mf * 16;
                ldsm_x4(ah[mf], aP + (uint32_t)((rb + a_row) * AS + ks + a_col) * 2);
            }
            #pragma unroll
            for (int p = 0; p < 4; p++) {
                int n0 = warp_n * 64 + p * 16;
                uint32_t b4[4];
                ldsm_x4(b4, bP + (uint32_t)((n0 + b_row) * AS + ks + b_col) * 2);
                #pragma unroll
                for (int mf = 0; mf < 2; mf++) {
                    mma16816(acc[mf][2 * p],     ah[mf], &b4[0]);
                    mma16816(acc[mf][2 * p + 1], ah[mf], &b4[2]);
                }
            }
        }

        if (nb) { storeA(buf ^ 1); CP_WAIT0(); }
        __syncthreads();
    }

    __half* dest = (half == 0) ? Cz : Ch;
    #pragma unroll
    for (int mf = 0; mf < 2; mf++) {
        int r_lo = row0 + warp_m * 32 + mf * 16 + g;
        int r_hi = r_lo + 8;
        #pragma unroll
        for (int nf = 0; nf < 8; nf++) {
            int col = warp_n * 64 + nf * 8 + tig * 2;
            float bx = 0.f, by = 0.f;
            if (half == 0) { bx = bias0[col]; by = bias0[col + 1]; }
            if (r_lo < n_rows)
                *reinterpret_cast<uint32_t*>(dest + (size_t)r_lo * NHID + col) =
                    pack_h2(__float2half_rn(acc[mf][nf][0] + bx), __float2half_rn(acc[mf][nf][1] + by));
            if (r_hi < n_rows)
                *reinterpret_cast<uint32_t*>(dest + (size_t)r_hi * NHID + col) =
                    pack_h2(__float2half_rn(acc[mf][nf][2] + bx), __float2half_rn(acc[mf][nf][3] + by));
        }
    }
}

// ---------------- GEMM2: split-K pipelined K=128, A fp16, B fp16 -> y2 fp16 ----------------
__global__ void __launch_bounds__(256, 2) gemm2_k128(
    const __half* __restrict__ A, int n_rows,
    const __half* __restrict__ B, __half* __restrict__ C)
{
    constexpr uint32_t matBytes = 128 * AS2 * 2;   // 34816
    extern __shared__ __half sm[];
    const uint32_t sbase = smem_u32(sm);
    const uint32_t aP = sbase;
    const uint32_t bP = sbase + matBytes;

    const int tid = threadIdx.x, wid = tid >> 5, lane = tid & 31;
    const int g = lane >> 2, tig = lane & 3;
    const int warp_m = wid & 3, warp_n = wid >> 2;
    const int row0 = blockIdx.x * 128;

    float acc[2][8][4];
    #pragma unroll
    for (int i = 0; i < 2; i++)
        #pragma unroll
        for (int j = 0; j < 8; j++)
            #pragma unroll
            for (int q = 0; q < 4; q++) acc[i][j][q] = 0.f;

    const int a_row = (lane & 7) + ((lane >> 3) & 1) * 8;
    const int a_col = ((lane >> 4) & 1) * 8;
    const int b_row = (lane & 7) + ((lane >> 4) & 1) * 8;
    const int b_col = ((lane >> 3) & 1) * 8;

    auto fillHalf = [&](int colbase) {
        #pragma unroll
        for (int it = 0; it < 4; it++) {
            int idx = it * 256 + tid;
            int r = idx >> 3, q = idx & 7;
            int c = colbase + q * 8;
            cpa16(aP + (uint32_t)(r * AS2 + c) * 2, A + (size_t)(row0 + r) * NHID + c);
        }
        #pragma unroll
        for (int it = 0; it < 4; it++) {
            int idx = it * 256 + tid;
            int r = idx >> 3, q = idx & 7;
            int c = colbase + q * 8;
            cpa16(bP + (uint32_t)(r * AS2 + c) * 2, B + (size_t)r * NHID + c);
        }
    };

    fillHalf(0);  CP_COMMIT();
    fillHalf(64); CP_COMMIT();

    CP_WAIT1();
    __syncthreads();

    auto computeHalf = [&](int ksbase) {
        #pragma unroll
        for (int ks0 = 0; ks0 < 64; ks0 += 16) {
            int ks = ksbase + ks0;
            uint32_t ah[2][4];
            #pragma unroll
            for (int mf = 0; mf < 2; mf++) {
                int rb = warp_m * 32 + mf * 16;
                ldsm_x4(ah[mf], aP + (uint32_t)((rb + a_row) * AS2 + ks + a_col) * 2);
            }
            #pragma unroll
            for (int p = 0; p < 4; p++) {
                int n0 = warp_n * 64 + p * 16;
                uint32_t b4[4];
                ldsm_x4(b4, bP + (uint32_t)((n0 + b_row) * AS2 + ks + b_col) * 2);
                #pragma unroll
                for (int mf = 0; mf < 2; mf++) {
                    mma16816(acc[mf][2 * p],     ah[mf], &b4[0]);
                    mma16816(acc[mf][2 * p + 1], ah[mf], &b4[2]);
                }
            }
        }
    };

    computeHalf(0);
    CP_WAIT0();
    __syncthreads();
    computeHalf(64);

    #pragma unroll
    for (int mf = 0; mf < 2; mf++) {
        int r_lo = row0 + warp_m * 32 + mf * 16 + g;
        int r_hi = r_lo + 8;
        #pragma unroll
        for (int nf = 0; nf < 8; nf++) {
            int col = warp_n * 64 + nf * 8 + tig * 2;
            if (r_lo < n_rows)
                *reinterpret_cast<uint32_t*>(C + (size_t)r_lo * NHID + col) =
                    pack_h2(__float2half_rn(acc[mf][nf][0]), __float2half_rn(acc[mf][nf][1]));
            if (r_hi < n_rows)
                *reinterpret_cast<uint32_t*>(C + (size_t)r_hi * NHID + col) =
                    pack_h2(__float2half_rn(acc[mf][nf][2]), __float2half_rn(acc[mf][nf][3]));
        }
    }
}

// ---------------- SpMM #1 (fp16 gather, unroll-8) + relu + residual(fp16) -> x1 fp16 ----------------
__global__ void spmm_relu_res(const int* __restrict__ col, const float* __restrict__ val,
                              const float* __restrict__ b1, int n) {
    int w = (blockIdx.x * blockDim.x + threadIdx.x) >> 5;
    int lane = threadIdx.x & 31;
    if (w >= n) return;
    int s = g_rowptr[w], e = g_rowptr[w + 1];
    const uint2* src = reinterpret_cast<const uint2*>(g_y1h);
    float a0[4] = {0.f, 0.f, 0.f, 0.f}, a1[4] = {0.f, 0.f, 0.f, 0.f};
    int i = s;
    for (; i + 7 < e; i += 8) {
        float v0 = __ldg(val + i),     v1 = __ldg(val + i + 1);
        float v2 = __ldg(val + i + 2), v3 = __ldg(val + i + 3);
        float v4 = __ldg(val + i + 4), v5 = __ldg(val + i + 5);
        float v6 = __ldg(val + i + 6), v7 = __ldg(val + i + 7);
        int c0 = __ldg(col + i),     c1 = __ldg(col + i + 1);
        int c2 = __ldg(col + i + 2), c3 = __ldg(col + i + 3);
        int c4 = __ldg(col + i + 4), c5 = __ldg(col + i + 5);
        int c6 = __ldg(col + i + 6), c7 = __ldg(col + i + 7);
        uint2 m0 = __ldg(src + (size_t)c0 * 32 + lane);
        uint2 m1 = __ldg(src + (size_t)c1 * 32 + lane);
        uint2 m2 = __ldg(src + (size_t)c2 * 32 + lane);
        uint2 m3 = __ldg(src + (size_t)c3 * 32 + lane);
        uint2 m4 = __ldg(src + (size_t)c4 * 32 + lane);
        uint2 m5 = __ldg(src + (size_t)c5 * 32 + lane);
        uint2 m6 = __ldg(src + (size_t)c6 * 32 + lane);
        uint2 m7 = __ldg(src + (size_t)c7 * 32 + lane);
        acc_gather(a0, m0, v0);
        acc_gather(a1, m1, v1);
        acc_gather(a0, m2, v2);
        acc_gather(a1, m3, v3);
        acc_gather(a0, m4, v4);
        acc_gather(a1, m5, v5);
        acc_gather(a0, m6, v6);
        acc_gather(a1, m7, v7);
    }
    if (i + 3 < e) {
        float v0 = __ldg(val + i),     v1 = __ldg(val + i + 1);
        float v2 = __ldg(val + i + 2), v3 = __ldg(val + i + 3);
        int c0 = __ldg(col + i),     c1 = __ldg(col + i + 1);
        int c2 = __ldg(col + i + 2), c3 = __ldg(col + i + 3);
        uint2 m0 = __ldg(src + (size_t)c0 * 32 + lane);
        uint2 m1 = __ldg(src + (size_t)c1 * 32 + lane);
        uint2 m2 = __ldg(src + (size_t)c2 * 32 + lane);
        uint2 m3 = __ldg(src + (size_t)c3 * 32 + lane);
        acc_gather(a0, m0, v0);
        acc_gather(a1, m1, v1);
        acc_gather(a0, m2, v2);
        acc_gather(a1, m3, v3);
        i += 4;
    }
    if (i + 1 < e) {
        float v0 = __ldg(val + i), v1 = __ldg(val + i + 1);
        int c0 = __ldg(col + i), c1 = __ldg(col + i + 1);
        uint2 m0 = __ldg(src + (size_t)c0 * 32 + lane);
        uint2 m1 = __ldg(src + (size_t)c1 * 32 + lane);
        acc_gather(a0, m0, v0);
        acc_gather(a1, m1, v1);
        i += 2;
    }
    if (i < e) {
        float v = __ldg(val + i); int c = __ldg(col + i);
        uint2 m = __ldg(src + (size_t)c * 32 + lane);
        acc_gather(a0, m, v);
    }
    #pragma unroll
    for (int q = 0; q < 4; q++) a0[q] += a1[q];
    float4 bb = reinterpret_cast<const float4*>(b1)[lane];
    uint2 zz = reinterpret_cast<const uint2*>(g_zh)[(size_t)w * 32 + lane];
    float2 z0 = __half22float2(*reinterpret_cast<__half2*>(&zz.x));
    float2 z1 = __half22float2(*reinterpret_cast<__half2*>(&zz.y));
    float rx = fmaxf(a0[0] + bb.x, 0.f) + z0.x;
    float ry = fmaxf(a0[1] + bb.y, 0.f) + z0.y;
    float rz = fmaxf(a0[2] + bb.z, 0.f) + z1.x;
    float rw = fmaxf(a0[3] + bb.w, 0.f) + z1.y;
    uint2 o = make_uint2(pack_h2(__float2half_rn(rx), __float2half_rn(ry)),
                         pack_h2(__float2half_rn(rz), __float2half_rn(rw)));
    reinterpret_cast<uint2*>(g_x1h)[(size_t)w * 32 + lane] = o;
}

// ---------------- SpMM #2 (fp16 gather, unroll-8) + bias + log_softmax -> fp32 out ----------------
__global__ void spmm_logsoftmax(const int* __restrict__ col, const float* __restrict__ val,
                                const float* __restrict__ b2, float* __restrict__ out, int n) {
    int w = (blockIdx.x * blockDim.x + threadIdx.x) >> 5;
    int lane = threadIdx.x & 31;
    if (w >= n) return;
    int s = g_rowptr[w], e = g_rowptr[w + 1];
    const uint2* src = reinterpret_cast<const uint2*>(g_y2h);
    float a0[4] = {0.f, 0.f, 0.f, 0.f}, a1[4] = {0.f, 0.f, 0.f, 0.f};
    int i = s;
    for (; i + 7 < e; i += 8) {
        float v0 = __ldg(val + i),     v1 = __ldg(val + i + 1);
        float v2 = __ldg(val + i + 2), v3 = __ldg(val + i + 3);
        float v4 = __ldg(val + i + 4), v5 = __ldg(val + i + 5);
        float v6 = __ldg(val + i + 6), v7 = __ldg(val + i + 7);
        int c0 = __ldg(col + i),     c1 = __ldg(col + i + 1);
        int c2 = __ldg(col + i + 2), c3 = __ldg(col + i + 3);
        int c4 = __ldg(col + i + 4), c5 = __ldg(col + i + 5);
        int c6 = __ldg(col + i + 6), c7 = __ldg(col + i + 7);
        uint2 m0 = __ldg(src + (size_t)c0 * 32 + lane);
        uint2 m1 = __ldg(src + (size_t)c1 * 32 + lane);
        uint2 m2 = __ldg(src + (size_t)c2 * 32 + lane);
        uint2 m3 = __ldg(src + (size_t)c3 * 32 + lane);
        uint2 m4 = __ldg(src + (size_t)c4 * 32 + lane);
        uint2 m5 = __ldg(src + (size_t)c5 * 32 + lane);
        uint2 m6 = __ldg(src + (size_t)c6 * 32 + lane);
        uint2 m7 = __ldg(src + (size_t)c7 * 32 + lane);
        acc_gather(a0, m0, v0);
        acc_gather(a1, m1, v1);
        acc_gather(a0, m2, v2);
        acc_gather(a1, m3, v3);
        acc_gather(a0, m4, v4);
        acc_gather(a1, m5, v5);
        acc_gather(a0, m6, v6);
        acc_gather(a1, m7, v7);
    }
    if (i + 3 < e) {
        float v0 = __ldg(val + i),     v1 = __ldg(val + i + 1);
        float v2 = __ldg(val + i + 2), v3 = __ldg(val + i + 3);
        int c0 = __ldg(col + i),     c1 = __ldg(col + i + 1);
        int c2 = __ldg(col + i + 2), c3 = __ldg(col + i + 3);
        uint2 m0 = __ldg(src + (size_t)c0 * 32 + lane);
        uint2 m1 = __ldg(src + (size_t)c1 * 32 + lane);
        uint2 m2 = __ldg(src + (size_t)c2 * 32 + lane);
        uint2 m3 = __ldg(src + (size_t)c3 * 32 + lane);
        acc_gather(a0, m0, v0);
        acc_gather(a1, m1, v1);
        acc_gather(a0, m2, v2);
        acc_gather(a1, m3, v3);
        i += 4;
    }
    if (i + 1 < e) {
        float v0 = __ldg(val + i), v1 = __ldg(val + i + 1);
        int c0 = __ldg(col + i), c1 = __ldg(col + i + 1);
        uint2 m0 = __ldg(src + (size_t)c0 * 32 + lane);
        uint2 m1 = __ldg(src + (size_t)c1 * 32 + lane);
        acc_gather(a0, m0, v0);
        acc_gather(a1, m1, v1);
        i += 2;
    }
    if (i < e) {
        float v = __ldg(val + i); int c = __ldg(col + i);
        uint2 m = __ldg(src + (size_t)c * 32 + lane);
        acc_gather(a0, m, v);
    }
    float4 bb = reinterpret_cast<const float4*>(b2)[lane];
    float hx = a0[0] + a1[0] + bb.x;
    float hy = a0[1] + a1[1] + bb.y;
    float hz = a0[2] + a1[2] + bb.z;
    float hw = a0[3] + a1[3] + bb.w;
    float mx = fmaxf(fmaxf(hx, hy), fmaxf(hz, hw));
    #pragma unroll
    for (int o = 16; o > 0; o >>= 1) mx = fmaxf(mx, __shfl_xor_sync(0xffffffffu, mx, o));
    float sum = expf(hx - mx) + expf(hy - mx) + expf(hz - mx) + expf(hw - mx);
    #pragma unroll
    for (int o = 16; o > 0; o >>= 1) sum += __shfl_xor_sync(0xffffffffu, sum, o);
    float lse = mx + logf(sum);
    float4 r = make_float4(hx - lse, hy - lse, hz - lse, hw - lse);
    reinterpret_cast<float4*>(out)[(size_t)w * 32 + lane] = r;
}

// ---------------- launch ----------------
extern "C" void kernel_launch(void* const* d_in, const int* in_sizes, int n_in,
                              void* d_out, int out_size) {
    const float* x        = (const float*)d_in[0];
    const int*   edge_row = (const int*)  d_in[1];
    const int*   edge_col = (const int*)  d_in[2];
    const float* edge_val = (const float*)d_in[3];
    const float* W_res    = (const float*)d_in[4];
    const float* b_res    = (const float*)d_in[5];
    const float* W1       = (const float*)d_in[6];
    const float* b1       = (const float*)d_in[7];
    const float* W2       = (const float*)d_in[8];
    const float* b2       = (const float*)d_in[9];
    float* out = (float*)d_out;
    const int n_nodes = in_sizes[0] / NFEAT;
    const int n_edges = in_sizes[1];

    __half *zp, *y1p, *x1p, *y2p, *bcp, *b2p;
    cudaGetSymbolAddress((void**)&zp,  g_zh);
    cudaGetSymbolAddress((void**)&y1p, g_y1h);
    cudaGetSymbolAddress((void**)&x1p, g_x1h);
    cudaGetSymbolAddress((void**)&y2p, g_y2h);
    cudaGetSymbolAddress((void**)&bcp, g_Bc);
    cudaGetSymbolAddress((void**)&b2p, g_B2);

    const int gemm1_smem = 4 * 128 * AS * 2;      // 40960
    const int gemm2_smem = 2 * 128 * AS2 * 2;     // 69632
    cudaFuncSetAttribute(gemm_a32,   cudaFuncAttributeMaxDynamicSharedMemorySize, gemm1_smem);
    cudaFuncSetAttribute(gemm2_k128, cudaFuncAttributeMaxDynamicSharedMemorySize, gemm2_smem);

    const int prep_threads = 2 * NHID * NFEAT + NHID * NHID + n_edges;
    prep_all<<<(prep_threads + 255) / 256, 256>>>(W_res, W1, W2, edge_row, n_edges, n_nodes);

    const int gx = (n_nodes + 127) / 128;
    dim3 g1(2, gx);
    gemm_a32<<<g1, 256, gemm1_smem>>>(x, NFEAT, NFEAT, n_nodes, bcp, zp, y1p, b_res);

    spmm_relu_res<<<(n_nodes * 32 + 255) / 256, 256>>>(edge_col, edge_val, b1, n_nodes);

    gemm2_k128<<<gx, 256, gemm2_smem>>>(x1p, n_nodes, b2p, y2p);

    spmm_logsoftmax<<<(n_nodes * 32 + 255) / 256, 256>>>(edge_col, edge_val, b2, out, n_nodes);
}